// round 5
// baseline (speedup 1.0000x reference)
#include <cuda_runtime.h>
#include <cuda_fp16.h>
#include <cstdint>

#define NU 200000
#define NI 100000
#define NE 3200000
#define DD 64

// ---------------- device scratch (static; no runtime allocation) ----------------
__device__ float  g_hu[NU * DD];
__device__ float  g_hi[NI * DD];
__device__ __half g_hu16[NU * DD];
__device__ __half g_hi16[NI * DD];
__device__ __half g_xu16[NU * DD];
__device__ __half g_xi16[NI * DD];
__device__ int    g_cnt_u[NU];
__device__ int    g_cnt_i[NI];
__device__ float  g_inv_u[NU];
__device__ float  g_inv_i[NI];
__device__ int    g_off_u[NU + 1];
__device__ int    g_off_i[NI + 1];
__device__ int    g_woff_u[NU];
__device__ int    g_woff_i[NI];
__device__ int    g_ssrc_u2i[NE];
__device__ int    g_ssrc_i2u[NE];
__device__ int    g_bsum_u[256];
__device__ int    g_bsum_i[256];

// ---------------- merged utility kernels ----------------
__global__ void zero2_k(int* __restrict__ a, int* __restrict__ b) {
    int i = blockIdx.x * blockDim.x + threadIdx.x;
    if (i < NI) a[i] = 0;
    if (i < NU) b[i] = 0;
}

__global__ void count2_k(const int* __restrict__ dst_u2i, const int* __restrict__ dst_i2u,
                         int* __restrict__ cnt_i, int* __restrict__ cnt_u) {
    for (int i = blockIdx.x * blockDim.x + threadIdx.x; i < 2 * NE; i += gridDim.x * blockDim.x) {
        if (i < NE) atomicAdd(&cnt_i[__ldg(&dst_u2i[i])], 1);
        else        atomicAdd(&cnt_u[__ldg(&dst_i2u[i - NE])], 1);
    }
}

__global__ void fill2_k(const int* __restrict__ src_u2i, const int* __restrict__ dst_u2i,
                        const int* __restrict__ src_i2u, const int* __restrict__ dst_i2u,
                        int* __restrict__ woff_i, int* __restrict__ woff_u,
                        int* __restrict__ ssrc_u2i, int* __restrict__ ssrc_i2u) {
    for (int i = blockIdx.x * blockDim.x + threadIdx.x; i < 2 * NE; i += gridDim.x * blockDim.x) {
        if (i < NE) {
            int d = __ldg(&dst_u2i[i]);
            int p = atomicAdd(&woff_i[d], 1);
            ssrc_u2i[p] = __ldg(&src_u2i[i]);
        } else {
            int d = __ldg(&dst_i2u[i - NE]);
            int p = atomicAdd(&woff_u[d], 1);
            ssrc_i2u[p] = __ldg(&src_i2u[i - NE]);
        }
    }
}

// fp32 -> fp16 shadows of both inputs in one kernel
__global__ void f2h2_k(const float* __restrict__ xu, const float* __restrict__ xi,
                       __half* __restrict__ yu, __half* __restrict__ yi) {
    int idx = (blockIdx.x * blockDim.x + threadIdx.x) << 2;
    if (idx < NU * DD) {
        float4 v = *(const float4*)(xu + idx);
        *(__half2*)(yu + idx) = __floats2half2_rn(v.x, v.y);
        *(__half2*)(yu + idx + 2) = __floats2half2_rn(v.z, v.w);
    } else {
        int j = idx - NU * DD;
        if (j < NI * DD) {
            float4 v = *(const float4*)(xi + j);
            *(__half2*)(yi + j) = __floats2half2_rn(v.x, v.y);
            *(__half2*)(yi + j + 2) = __floats2half2_rn(v.z, v.w);
        }
    }
}

// ---------------- scans (counts -> offsets + inv degree) ----------------
__global__ void block_sum_k(const int* __restrict__ cnt, int* __restrict__ bsum, int n) {
    __shared__ int s[1024];
    int i = blockIdx.x * 1024 + threadIdx.x;
    int v = (i < n) ? cnt[i] : 0;
    s[threadIdx.x] = v;
    __syncthreads();
    for (int st = 512; st > 0; st >>= 1) {
        if (threadIdx.x < st) s[threadIdx.x] += s[threadIdx.x + st];
        __syncthreads();
    }
    if (threadIdx.x == 0) bsum[blockIdx.x] = s[0];
}

__global__ void scan_bsum_k(int* __restrict__ bsum, int nb) {
    __shared__ int s[1024];
    int v = (threadIdx.x < nb) ? bsum[threadIdx.x] : 0;
    s[threadIdx.x] = v;
    __syncthreads();
    for (int o = 1; o < 1024; o <<= 1) {
        int t = (threadIdx.x >= o) ? s[threadIdx.x - o] : 0;
        __syncthreads();
        s[threadIdx.x] += t;
        __syncthreads();
    }
    if (threadIdx.x < nb) bsum[threadIdx.x] = s[threadIdx.x] - v;  // exclusive
}

__global__ void scan_write_k(const int* __restrict__ cnt, const int* __restrict__ bsum,
                             int* __restrict__ off, int* __restrict__ woff,
                             float* __restrict__ inv, int n) {
    __shared__ int s[1024];
    int i = blockIdx.x * 1024 + threadIdx.x;
    int v = (i < n) ? cnt[i] : 0;
    s[threadIdx.x] = v;
    __syncthreads();
    for (int o = 1; o < 1024; o <<= 1) {
        int t = (threadIdx.x >= o) ? s[threadIdx.x - o] : 0;
        __syncthreads();
        s[threadIdx.x] += t;
        __syncthreads();
    }
    int excl = s[threadIdx.x] - v + bsum[blockIdx.x];
    if (i < n) {
        off[i] = excl; woff[i] = excl;
        inv[i] = 1.0f / (float)max(v, 1);
    }
    if (i == n - 1) off[n] = excl + v;
}

// ---------------- fused gather-aggregate + GEMM(FFMA2) + bias + LN + ReLU -------
// Per tile of 64 nodes:
//   phase 1 (gather): warp w owns nodes w*8..w*8+7; lane l owns dims (2l, 2l+1).
//     mean-aggregate fp16 neighbor rows (fp32 accum), load fp32 root row,
//     store both as float2 into sIn[node][kk] (node-major, coalesced, conflict-free).
//     kk 0..31 = agg dims 2kk,2kk+1 ; kk 32..63 = root dims 2(kk-32), 2(kk-32)+1.
//   phase 2 (GEMM): thread (d = tid&63, ty = tid>>6) computes 16 nodes for dim d:
//     acc2[j] += sIn[node][kk] * sWT[d][kk]  (fma.rn.f32x2 over k-pairs)
//     where sWT[d][kk] = {Wcat[2kk][d], Wcat[2kk+1][d]}, Wcat = [Wrel ; Wroot + I].
//   phase 3: bias + horizontal add -> sOut[node][d]; LN + ReLU -> gmem.
#define SWT_F2     (64 * 65)                 // [d][kk] float2, padded stride 65
#define SIN_F2     (64 * 64)                 // [node][kk] float2
#define FUSED_SMEM ((SWT_F2 + SIN_F2) * 8)   // 66048 bytes

__global__ __launch_bounds__(256, 3) void fused_k(
    const __half* __restrict__ src16,   // gather source features (fp16)
    const int* __restrict__ roff, const int* __restrict__ ssrc,
    const float* __restrict__ inv,
    const float* __restrict__ hroot,    // fp32 root features
    const float* __restrict__ Wrel, const float* __restrict__ Wroot,
    const float* __restrict__ bias, const float* __restrict__ gam,
    const float* __restrict__ bet,
    float* __restrict__ out, __half* __restrict__ out16, int n) {
    extern __shared__ float smem[];
    float2* sWT = (float2*)smem;
    float2* sIn = ((float2*)smem) + SWT_F2;
    float*  sOut = (float*)sIn;          // reuse (16KB of the 32KB sIn region)
    int tid = threadIdx.x;
    int lane = tid & 31, wid = tid >> 5;

    // ---- load + transpose weights once per CTA (with +I residual fold) ----
    for (int i = tid; i < 64 * 64; i += 256) {
        int d = i & 63, kk = i >> 6;
        float w0, w1;
        if (kk < 32) {
            w0 = __ldg(&Wrel[(2 * kk) * 64 + d]);
            w1 = __ldg(&Wrel[(2 * kk + 1) * 64 + d]);
        } else {
            int r0 = 2 * kk - 64, r1 = r0 + 1;
            w0 = __ldg(&Wroot[r0 * 64 + d]) + (r0 == d ? 1.0f : 0.0f);
            w1 = __ldg(&Wroot[r1 * 64 + d]) + (r1 == d ? 1.0f : 0.0f);
        }
        sWT[d * 65 + kk] = make_float2(w0, w1);
    }

    int d = tid & 63;
    int ty = tid >> 6;
    float bd = __ldg(&bias[d]);
    float gg0 = __ldg(&gam[lane]), gg1 = __ldg(&gam[lane + 32]);
    float bb0 = __ldg(&bet[lane]), bb1 = __ldg(&bet[lane + 32]);
    int ntiles = (n + 63) >> 6;

    for (int tile = blockIdx.x; tile < ntiles; tile += gridDim.x) {
        int base = tile << 6;
        __syncthreads();  // sWT ready (iter 0) / prior LN reads done

        // ---- phase 1: gather-aggregate + root load, write sIn ----
        for (int j = 0; j < 8; j++) {
            int node = wid * 8 + j;
            int gn = base + node;
            float ax = 0.f, ay = 0.f;
            float2 hr = make_float2(0.f, 0.f);
            if (gn < n) {
                int b0 = __ldg(&roff[gn]), b1 = __ldg(&roff[gn + 1]);
                for (int e = b0; e < b1; e += 32) {
                    int rem = b1 - e;
                    int idx = (lane < rem) ? __ldg(&ssrc[e + lane]) : 0;
                    if (rem >= 32) {
#pragma unroll
                        for (int j2 = 0; j2 < 32; j2++) {
                            int s = __shfl_sync(0xffffffffu, idx, j2);
                            __half2 v = *(const __half2*)(src16 + (size_t)s * DD + 2 * lane);
                            float2 f = __half22float2(v);
                            ax += f.x; ay += f.y;
                        }
                    } else {
                        for (int j2 = 0; j2 < rem; j2++) {
                            int s = __shfl_sync(0xffffffffu, idx, j2);
                            __half2 v = *(const __half2*)(src16 + (size_t)s * DD + 2 * lane);
                            float2 f = __half22float2(v);
                            ax += f.x; ay += f.y;
                        }
                    }
                }
                float iv = __ldg(&inv[gn]);
                ax *= iv; ay *= iv;
                hr = *(const float2*)(hroot + (size_t)gn * DD + 2 * lane);
            }
            sIn[node * 64 + lane] = make_float2(ax, ay);
            sIn[node * 64 + 32 + lane] = hr;
        }
        __syncthreads();

        // ---- phase 2: FFMA2 GEMM over k-pairs ----
        unsigned long long acc[16];
#pragma unroll
        for (int j = 0; j < 16; j++) acc[j] = 0ull;
        const unsigned long long* wrow = (const unsigned long long*)(sWT + d * 65);
        const unsigned long long* xbase = (const unsigned long long*)(sIn + (ty * 16) * 64);
#pragma unroll 2
        for (int kk = 0; kk < 64; kk++) {
            unsigned long long w2 = wrow[kk];
#pragma unroll
            for (int j = 0; j < 16; j++) {
                unsigned long long x2 = xbase[j * 64 + kk];
                asm("fma.rn.f32x2 %0, %1, %2, %0;" : "+l"(acc[j]) : "l"(x2), "l"(w2));
            }
        }
        __syncthreads();  // done reading sIn -> safe to overwrite via sOut alias

        // ---- phase 3a: horizontal add + bias -> sOut[node][d] ----
#pragma unroll
        for (int j = 0; j < 16; j++) {
            float lo, hi;
            asm("mov.b64 {%0, %1}, %2;" : "=f"(lo), "=f"(hi) : "l"(acc[j]));
            sOut[(ty * 16 + j) * 64 + d] = lo + hi + bd;
        }
        __syncthreads();

        // ---- phase 3b: LayerNorm + ReLU, warp w handles nodes w*8..w*8+7 ----
#pragma unroll
        for (int jj = 0; jj < 8; jj++) {
            int node = wid * 8 + jj;
            int gn = base + node;
            if (gn >= n) break;
            float x0 = sOut[node * 64 + lane];
            float x1 = sOut[node * 64 + 32 + lane];
            float s = x0 + x1;
#pragma unroll
            for (int o = 16; o; o >>= 1) s += __shfl_xor_sync(0xffffffffu, s, o);
            float m = s * 0.015625f;
            float e0 = x0 - m, e1 = x1 - m;
            float v = e0 * e0 + e1 * e1;
#pragma unroll
            for (int o = 16; o; o >>= 1) v += __shfl_xor_sync(0xffffffffu, v, o);
            float r = rsqrtf(v * 0.015625f + 1e-5f);
            float y0 = fmaxf(fmaf(e0 * r, gg0, bb0), 0.f);
            float y1 = fmaxf(fmaf(e1 * r, gg1, bb1), 0.f);
            out[(size_t)gn * DD + lane] = y0;
            out[(size_t)gn * DD + 32 + lane] = y1;
            if (out16) {
                out16[(size_t)gn * DD + lane] = __float2half_rn(y0);
                out16[(size_t)gn * DD + 32 + lane] = __float2half_rn(y1);
            }
        }
    }
}

// ---------------- launch ----------------
extern "C" void kernel_launch(void* const* d_in, const int* in_sizes, int n_in,
                              void* d_out, int out_size) {
    const float* x_user     = (const float*)d_in[0];
    const float* x_item     = (const float*)d_in[1];
    const int*   src_u2i    = (const int*)d_in[2];
    const int*   dst_u2i    = (const int*)d_in[3];
    const int*   src_i2u    = (const int*)d_in[4];
    const int*   dst_i2u    = (const int*)d_in[5];
    const float* W_rel_u2i  = (const float*)d_in[6];
    const float* W_root_u2i = (const float*)d_in[7];
    const float* b_u2i      = (const float*)d_in[8];
    const float* W_rel_i2u  = (const float*)d_in[9];
    const float* W_root_i2u = (const float*)d_in[10];
    const float* b_i2u      = (const float*)d_in[11];
    const float* ln_g_user  = (const float*)d_in[12];
    const float* ln_b_user  = (const float*)d_in[13];
    const float* ln_g_item  = (const float*)d_in[14];
    const float* ln_b_item  = (const float*)d_in[15];
    float* out = (float*)d_out;

    float *p_hu, *p_hi, *p_inv_u, *p_inv_i;
    __half *p_hu16, *p_hi16, *p_xu16, *p_xi16;
    int *p_cnt_u, *p_cnt_i, *p_off_u, *p_off_i, *p_woff_u, *p_woff_i;
    int *p_ssrc_u2i, *p_ssrc_i2u, *p_bsum_u, *p_bsum_i;
    cudaGetSymbolAddress((void**)&p_hu, g_hu);
    cudaGetSymbolAddress((void**)&p_hi, g_hi);
    cudaGetSymbolAddress((void**)&p_hu16, g_hu16);
    cudaGetSymbolAddress((void**)&p_hi16, g_hi16);
    cudaGetSymbolAddress((void**)&p_xu16, g_xu16);
    cudaGetSymbolAddress((void**)&p_xi16, g_xi16);
    cudaGetSymbolAddress((void**)&p_inv_u, g_inv_u);
    cudaGetSymbolAddress((void**)&p_inv_i, g_inv_i);
    cudaGetSymbolAddress((void**)&p_cnt_u, g_cnt_u);
    cudaGetSymbolAddress((void**)&p_cnt_i, g_cnt_i);
    cudaGetSymbolAddress((void**)&p_off_u, g_off_u);
    cudaGetSymbolAddress((void**)&p_off_i, g_off_i);
    cudaGetSymbolAddress((void**)&p_woff_u, g_woff_u);
    cudaGetSymbolAddress((void**)&p_woff_i, g_woff_i);
    cudaGetSymbolAddress((void**)&p_ssrc_u2i, g_ssrc_u2i);
    cudaGetSymbolAddress((void**)&p_ssrc_i2u, g_ssrc_i2u);
    cudaGetSymbolAddress((void**)&p_bsum_u, g_bsum_u);
    cudaGetSymbolAddress((void**)&p_bsum_i, g_bsum_i);

    cudaFuncSetAttribute(fused_k, cudaFuncAttributeMaxDynamicSharedMemorySize,
                         FUSED_SMEM);

    const int TB = 256;
    const int nbI = (NI + 1023) / 1024;  // 98
    const int nbU = (NU + 1023) / 1024;  // 196

    // --- CSR build (edge indices are layer-invariant) ---
    zero2_k<<<(NU + TB - 1) / TB, TB>>>(p_cnt_i, p_cnt_u);
    count2_k<<<(2 * NE + TB - 1) / TB, TB>>>(dst_u2i, dst_i2u, p_cnt_i, p_cnt_u);
    block_sum_k<<<nbI, 1024>>>(p_cnt_i, p_bsum_i, NI);
    scan_bsum_k<<<1, 1024>>>(p_bsum_i, nbI);
    scan_write_k<<<nbI, 1024>>>(p_cnt_i, p_bsum_i, p_off_i, p_woff_i, p_inv_i, NI);
    block_sum_k<<<nbU, 1024>>>(p_cnt_u, p_bsum_u, NU);
    scan_bsum_k<<<1, 1024>>>(p_bsum_u, nbU);
    scan_write_k<<<nbU, 1024>>>(p_cnt_u, p_bsum_u, p_off_u, p_woff_u, p_inv_u, NU);
    fill2_k<<<(2 * NE + TB - 1) / TB, TB>>>(src_u2i, dst_u2i, src_i2u, dst_i2u,
                                            p_woff_i, p_woff_u, p_ssrc_u2i, p_ssrc_i2u);
    f2h2_k<<<((NU + NI) * DD / 4 + TB - 1) / TB, TB>>>(x_user, x_item, p_xu16, p_xi16);

    const int GRID = 444;  // 3 CTAs/SM x 148 SMs

    // --- layer 0 ---
    fused_k<<<GRID, TB, FUSED_SMEM>>>(p_xu16, p_off_i, p_ssrc_u2i, p_inv_i, x_item,
                                      W_rel_u2i, W_root_u2i, b_u2i,
                                      ln_g_item, ln_b_item, p_hi, p_hi16, NI);
    fused_k<<<GRID, TB, FUSED_SMEM>>>(p_xi16, p_off_u, p_ssrc_i2u, p_inv_u, x_user,
                                      W_rel_i2u, W_root_i2u, b_i2u,
                                      ln_g_user, ln_b_user, p_hu, p_hu16, NU);

    // --- layer 1 (writes d_out: users first, then items) ---
    fused_k<<<GRID, TB, FUSED_SMEM>>>(p_hu16, p_off_i, p_ssrc_u2i, p_inv_i, p_hi,
                                      W_rel_u2i + 4096, W_root_u2i + 4096, b_u2i + 64,
                                      ln_g_item + 64, ln_b_item + 64,
                                      out + (size_t)NU * DD, (__half*)0, NI);
    fused_k<<<GRID, TB, FUSED_SMEM>>>(p_hi16, p_off_u, p_ssrc_i2u, p_inv_u, p_hu,
                                      W_rel_i2u + 4096, W_root_i2u + 4096, b_i2u + 64,
                                      ln_g_user + 64, ln_b_user + 64,
                                      out, (__half*)0, NU);
}

// round 7
// speedup vs baseline: 1.3317x; 1.3317x over previous
#include <cuda_runtime.h>
#include <cuda_fp16.h>
#include <cstdint>

#define NU 200000
#define NI 100000
#define NE 3200000
#define DD 64
#define NBI 98   // ceil(NI/1024)
#define NBU 196  // ceil(NU/1024)

// ---------------- device scratch (static; no runtime allocation) ----------------
__device__ float  g_hu[NU * DD];
__device__ float  g_hi[NI * DD];
__device__ __half g_hu16[NU * DD];
__device__ __half g_hi16[NI * DD];
__device__ __half g_xu16[NU * DD];
__device__ __half g_xi16[NI * DD];
__device__ __half g_agg_u16[NU * DD];
__device__ __half g_agg_i16[NI * DD];
__device__ int    g_cnt_u[NU];
__device__ int    g_cnt_i[NI];
__device__ float  g_inv_u[NU];
__device__ float  g_inv_i[NI];
__device__ int    g_off_u[NU + 1];
__device__ int    g_off_i[NI + 1];
__device__ int    g_woff_u[NU];
__device__ int    g_woff_i[NI];
__device__ int    g_ssrc_u2i[NE];
__device__ int    g_ssrc_i2u[NE];
__device__ int    g_bsum_u[256];
__device__ int    g_bsum_i[256];

// ---------------- launch 1: zero counters + fp16 shadows of inputs ----------------
__global__ void prep_k(const float* __restrict__ xu, const float* __restrict__ xi,
                       __half* __restrict__ yu, __half* __restrict__ yi,
                       int* __restrict__ cnt_i, int* __restrict__ cnt_u) {
    int i = blockIdx.x * blockDim.x + threadIdx.x;
    if (i < NI) cnt_i[i] = 0;
    if (i < NU) cnt_u[i] = 0;
    int idx = i << 2;
    if (idx < NU * DD) {
        float4 v = *(const float4*)(xu + idx);
        *(__half2*)(yu + idx) = __floats2half2_rn(v.x, v.y);
        *(__half2*)(yu + idx + 2) = __floats2half2_rn(v.z, v.w);
    } else {
        int j = idx - NU * DD;
        if (j < NI * DD) {
            float4 v = *(const float4*)(xi + j);
            *(__half2*)(yi + j) = __floats2half2_rn(v.x, v.y);
            *(__half2*)(yi + j + 2) = __floats2half2_rn(v.z, v.w);
        }
    }
}

// ---------------- launch 2: degree count for both edge sets ----------------
__global__ void count2_k(const int* __restrict__ dst_u2i, const int* __restrict__ dst_i2u,
                         int* __restrict__ cnt_i, int* __restrict__ cnt_u) {
    for (int i = blockIdx.x * blockDim.x + threadIdx.x; i < 2 * NE; i += gridDim.x * blockDim.x) {
        if (i < NE) atomicAdd(&cnt_i[__ldg(&dst_u2i[i])], 1);
        else        atomicAdd(&cnt_u[__ldg(&dst_i2u[i - NE])], 1);
    }
}

// ---------------- launch 3: per-block sums for both sets ----------------
__global__ void bsum2_k(const int* __restrict__ cnt_i, const int* __restrict__ cnt_u,
                        int* __restrict__ bsum_i, int* __restrict__ bsum_u) {
    __shared__ int s[1024];
    int bb = blockIdx.x;
    const int* cnt; int* bsum; int n;
    if (bb < NBI) { cnt = cnt_i; bsum = bsum_i; n = NI; }
    else          { bb -= NBI; cnt = cnt_u; bsum = bsum_u; n = NU; }
    int i = bb * 1024 + threadIdx.x;
    int v = (i < n) ? cnt[i] : 0;
    s[threadIdx.x] = v;
    __syncthreads();
    for (int st = 512; st > 0; st >>= 1) {
        if (threadIdx.x < st) s[threadIdx.x] += s[threadIdx.x + st];
        __syncthreads();
    }
    if (threadIdx.x == 0) bsum[bb] = s[0];
}

// ---------------- launch 4: offsets + inv degree (inline bsum prefix) ----------------
__global__ void swrite2_k(const int* __restrict__ cnt_i, const int* __restrict__ cnt_u,
                          const int* __restrict__ bsum_i, const int* __restrict__ bsum_u,
                          int* __restrict__ off_i, int* __restrict__ off_u,
                          int* __restrict__ woff_i, int* __restrict__ woff_u,
                          float* __restrict__ inv_i, float* __restrict__ inv_u) {
    __shared__ int s[1024];
    __shared__ int p[256];
    int bb = blockIdx.x;
    const int* cnt; const int* bsum; int* off; int* woff; float* inv; int n;
    if (bb < NBI) { cnt = cnt_i; bsum = bsum_i; off = off_i; woff = woff_i; inv = inv_i; n = NI; }
    else { bb -= NBI; cnt = cnt_u; bsum = bsum_u; off = off_u; woff = woff_u; inv = inv_u; n = NU; }
    // prefix = sum of bsum[0..bb)
    if (threadIdx.x < 256) p[threadIdx.x] = (threadIdx.x < bb) ? bsum[threadIdx.x] : 0;
    __syncthreads();
    for (int st = 128; st > 0; st >>= 1) {
        if (threadIdx.x < st) p[threadIdx.x] += p[threadIdx.x + st];
        __syncthreads();
    }
    int prefix = p[0];
    // block-local inclusive scan
    int i = bb * 1024 + threadIdx.x;
    int v = (i < n) ? cnt[i] : 0;
    s[threadIdx.x] = v;
    __syncthreads();
    for (int o = 1; o < 1024; o <<= 1) {
        int t = (threadIdx.x >= o) ? s[threadIdx.x - o] : 0;
        __syncthreads();
        s[threadIdx.x] += t;
        __syncthreads();
    }
    int excl = s[threadIdx.x] - v + prefix;
    if (i < n) {
        off[i] = excl; woff[i] = excl;
        inv[i] = 1.0f / (float)max(v, 1);
    }
    if (i == n - 1) off[n] = excl + v;
}

// ---------------- launch 5: CSR fill for both edge sets ----------------
__global__ void fill2_k(const int* __restrict__ src_u2i, const int* __restrict__ dst_u2i,
                        const int* __restrict__ src_i2u, const int* __restrict__ dst_i2u,
                        int* __restrict__ woff_i, int* __restrict__ woff_u,
                        int* __restrict__ ssrc_u2i, int* __restrict__ ssrc_i2u) {
    for (int i = blockIdx.x * blockDim.x + threadIdx.x; i < 2 * NE; i += gridDim.x * blockDim.x) {
        if (i < NE) {
            int d = __ldg(&dst_u2i[i]);
            int p2 = atomicAdd(&woff_i[d], 1);
            ssrc_u2i[p2] = __ldg(&src_u2i[i]);
        } else {
            int d = __ldg(&dst_i2u[i - NE]);
            int p2 = atomicAdd(&woff_u[d], 1);
            ssrc_i2u[p2] = __ldg(&src_i2u[i - NE]);
        }
    }
}

// ---------------- fp16 mean-aggregation (gather; fp32 accum; fp16 out) ----------
// 16 threads per destination node; each owns 4 halves (8 bytes) of the 64-dim row.
__global__ void agg16_k(const __half* __restrict__ h16, const int* __restrict__ roff,
                        const int* __restrict__ ssrc, const float* __restrict__ inv,
                        __half* __restrict__ agg16, int n) {
    int t = blockIdx.x * blockDim.x + threadIdx.x;
    int node = t >> 4;
    if (node >= n) return;
    int q = (t & 15) << 2;  // half offset
    int b0 = __ldg(&roff[node]), b1 = __ldg(&roff[node + 1]);
    float ax = 0.f, ay = 0.f, az = 0.f, aw = 0.f;
    int i = b0;
    for (; i + 4 <= b1; i += 4) {
        int s0 = __ldg(&ssrc[i]),     s1 = __ldg(&ssrc[i + 1]);
        int s2 = __ldg(&ssrc[i + 2]), s3 = __ldg(&ssrc[i + 3]);
        uint2 v0 = *(const uint2*)(h16 + (size_t)s0 * DD + q);
        uint2 v1 = *(const uint2*)(h16 + (size_t)s1 * DD + q);
        uint2 v2 = *(const uint2*)(h16 + (size_t)s2 * DD + q);
        uint2 v3 = *(const uint2*)(h16 + (size_t)s3 * DD + q);
        float2 f;
        f = __half22float2(*(__half2*)&v0.x); ax += f.x; ay += f.y;
        f = __half22float2(*(__half2*)&v0.y); az += f.x; aw += f.y;
        f = __half22float2(*(__half2*)&v1.x); ax += f.x; ay += f.y;
        f = __half22float2(*(__half2*)&v1.y); az += f.x; aw += f.y;
        f = __half22float2(*(__half2*)&v2.x); ax += f.x; ay += f.y;
        f = __half22float2(*(__half2*)&v2.y); az += f.x; aw += f.y;
        f = __half22float2(*(__half2*)&v3.x); ax += f.x; ay += f.y;
        f = __half22float2(*(__half2*)&v3.y); az += f.x; aw += f.y;
    }
    for (; i < b1; i++) {
        int s = __ldg(&ssrc[i]);
        uint2 v = *(const uint2*)(h16 + (size_t)s * DD + q);
        float2 f;
        f = __half22float2(*(__half2*)&v.x); ax += f.x; ay += f.y;
        f = __half22float2(*(__half2*)&v.y); az += f.x; aw += f.y;
    }
    float iv = __ldg(&inv[node]);
    ax *= iv; ay *= iv; az *= iv; aw *= iv;
    uint2 o;
    *(__half2*)&o.x = __floats2half2_rn(ax, ay);
    *(__half2*)&o.y = __floats2half2_rn(az, aw);
    *(uint2*)(agg16 + (size_t)node * DD + q) = o;
}

// ---------------- GEMM (FFMA2 over k-pairs) + bias + LN + ReLU ------------------
// out = relu(LN([agg , h] @ [Wrel ; Wroot+I] + b))    (mean & residual pre-folded)
// TILE=32 nodes/CTA-iter, 256 threads. Thread (d=tid&63, ty=tid>>6) owns 8 nodes.
// sIn[node][kk] float2 (node-major, conflict-free staging, broadcast mainloop reads);
// sWT[d][kk] float2 = {Wcat[2kk][d], Wcat[2kk+1][d]}.
#define SWT_F2    (64 * 65)
#define SIN_F2    (32 * 64)
#define COMP_SMEM ((SWT_F2 + SIN_F2) * 8)   // 49664 bytes

__global__ __launch_bounds__(256, 4) void comp_k(
    const __half* __restrict__ agg16,
    const float* __restrict__ hroot,
    const float* __restrict__ Wrel, const float* __restrict__ Wroot,
    const float* __restrict__ bias, const float* __restrict__ gam,
    const float* __restrict__ bet,
    float* __restrict__ out, __half* __restrict__ out16, int n) {
    extern __shared__ float smem[];
    float2* sWT = (float2*)smem;
    float2* sIn = ((float2*)smem) + SWT_F2;
    float*  sOut = (float*)sIn;   // alias: 8KB of the 16KB sIn region
    int tid = threadIdx.x;
    int lane = tid & 31, wid = tid >> 5;

    // weights, transposed to [d][kk] pairs, residual identity folded in
    for (int i = tid; i < 64 * 64; i += 256) {
        int d = i & 63, kk = i >> 6;
        float w0, w1;
        if (kk < 32) {
            w0 = __ldg(&Wrel[(2 * kk) * 64 + d]);
            w1 = __ldg(&Wrel[(2 * kk + 1) * 64 + d]);
        } else {
            int r0 = 2 * kk - 64, r1 = r0 + 1;
            w0 = __ldg(&Wroot[r0 * 64 + d]) + (r0 == d ? 1.0f : 0.0f);
            w1 = __ldg(&Wroot[r1 * 64 + d]) + (r1 == d ? 1.0f : 0.0f);
        }
        sWT[d * 65 + kk] = make_float2(w0, w1);
    }

    int d = tid & 63;
    int ty = tid >> 6;
    float bd = __ldg(&bias[d]);
    float gg0 = __ldg(&gam[lane]), gg1 = __ldg(&gam[lane + 32]);
    float bb0 = __ldg(&bet[lane]), bb1 = __ldg(&bet[lane + 32]);
    int ntiles = n >> 5;  // n multiple of 32

    for (int tile = blockIdx.x; tile < ntiles; tile += gridDim.x) {
        int base = tile << 5;
        __syncthreads();  // sWT ready (iter 0) / prior LN smem reads done

        // stage 32 nodes: agg (fp16->fp32) pairs kk 0..31, root fp32 pairs kk 32..63
        for (int i = tid; i < 512; i += 256) {
            int node = i >> 4;
            int gn = base + node;
            int qq = (i & 15) << 2;
            int kk = qq >> 1;
            uint2 av = *(const uint2*)(agg16 + (size_t)gn * DD + qq);
            float2 a0 = __half22float2(*(__half2*)&av.x);
            float2 a1 = __half22float2(*(__half2*)&av.y);
            float4 hh = *(const float4*)(hroot + (size_t)gn * DD + qq);
            sIn[node * 64 + kk]     = a0;
            sIn[node * 64 + kk + 1] = a1;
            sIn[node * 64 + 32 + kk]     = make_float2(hh.x, hh.y);
            sIn[node * 64 + 32 + kk + 1] = make_float2(hh.z, hh.w);
        }
        __syncthreads();

        unsigned long long acc[8];
#pragma unroll
        for (int j = 0; j < 8; j++) acc[j] = 0ull;
        const unsigned long long* wrow = (const unsigned long long*)(sWT + d * 65);
        const unsigned long long* xb = (const unsigned long long*)(sIn + (ty * 8) * 64);
#pragma unroll 4
        for (int kk = 0; kk < 64; kk++) {
            unsigned long long w2 = wrow[kk];
#pragma unroll
            for (int j = 0; j < 8; j++) {
                unsigned long long x2 = xb[j * 64 + kk];
                asm("fma.rn.f32x2 %0, %1, %2, %0;" : "+l"(acc[j]) : "l"(x2), "l"(w2));
            }
        }
        __syncthreads();  // done reading sIn -> safe to overwrite via sOut alias

        // horizontal add + bias
#pragma unroll
        for (int j = 0; j < 8; j++) {
            float lo, hi;
            asm("mov.b64 {%0, %1}, %2;" : "=f"(lo), "=f"(hi) : "l"(acc[j]));
            sOut[(ty * 8 + j) * 64 + d] = lo + hi + bd;
        }
        __syncthreads();

        // LayerNorm + ReLU: warp wid handles nodes wid*4 .. wid*4+3
#pragma unroll
        for (int jj = 0; jj < 4; jj++) {
            int node = (wid << 2) + jj;
            int gn = base + node;
            float x0 = sOut[node * 64 + lane];
            float x1 = sOut[node * 64 + 32 + lane];
            float s = x0 + x1;
#pragma unroll
            for (int o = 16; o; o >>= 1) s += __shfl_xor_sync(0xffffffffu, s, o);
            float m = s * 0.015625f;
            float e0 = x0 - m, e1 = x1 - m;
            float v = e0 * e0 + e1 * e1;
#pragma unroll
            for (int o = 16; o; o >>= 1) v += __shfl_xor_sync(0xffffffffu, v, o);
            float r = rsqrtf(v * 0.015625f + 1e-5f);
            float y0 = fmaxf(fmaf(e0 * r, gg0, bb0), 0.f);
            float y1 = fmaxf(fmaf(e1 * r, gg1, bb1), 0.f);
            out[(size_t)gn * DD + lane] = y0;
            out[(size_t)gn * DD + 32 + lane] = y1;
            if (out16) {
                out16[(size_t)gn * DD + lane] = __float2half_rn(y0);
                out16[(size_t)gn * DD + 32 + lane] = __float2half_rn(y1);
            }
        }
    }
}

// ---------------- launch ----------------
extern "C" void kernel_launch(void* const* d_in, const int* in_sizes, int n_in,
                              void* d_out, int out_size) {
    const float* x_user     = (const float*)d_in[0];
    const float* x_item     = (const float*)d_in[1];
    const int*   src_u2i    = (const int*)d_in[2];
    const int*   dst_u2i    = (const int*)d_in[3];
    const int*   src_i2u    = (const int*)d_in[4];
    const int*   dst_i2u    = (const int*)d_in[5];
    const float* W_rel_u2i  = (const float*)d_in[6];
    const float* W_root_u2i = (const float*)d_in[7];
    const float* b_u2i      = (const float*)d_in[8];
    const float* W_rel_i2u  = (const float*)d_in[9];
    const float* W_root_i2u = (const float*)d_in[10];
    const float* b_i2u      = (const float*)d_in[11];
    const float* ln_g_user  = (const float*)d_in[12];
    const float* ln_b_user  = (const float*)d_in[13];
    const float* ln_g_item  = (const float*)d_in[14];
    const float* ln_b_item  = (const float*)d_in[15];
    float* out = (float*)d_out;

    float *p_hu, *p_hi, *p_inv_u, *p_inv_i;
    __half *p_hu16, *p_hi16, *p_xu16, *p_xi16, *p_agg_u16, *p_agg_i16;
    int *p_cnt_u, *p_cnt_i, *p_off_u, *p_off_i, *p_woff_u, *p_woff_i;
    int *p_ssrc_u2i, *p_ssrc_i2u, *p_bsum_u, *p_bsum_i;
    cudaGetSymbolAddress((void**)&p_hu, g_hu);
    cudaGetSymbolAddress((void**)&p_hi, g_hi);
    cudaGetSymbolAddress((void**)&p_hu16, g_hu16);
    cudaGetSymbolAddress((void**)&p_hi16, g_hi16);
    cudaGetSymbolAddress((void**)&p_xu16, g_xu16);
    cudaGetSymbolAddress((void**)&p_xi16, g_xi16);
    cudaGetSymbolAddress((void**)&p_agg_u16, g_agg_u16);
    cudaGetSymbolAddress((void**)&p_agg_i16, g_agg_i16);
    cudaGetSymbolAddress((void**)&p_inv_u, g_inv_u);
    cudaGetSymbolAddress((void**)&p_inv_i, g_inv_i);
    cudaGetSymbolAddress((void**)&p_cnt_u, g_cnt_u);
    cudaGetSymbolAddress((void**)&p_cnt_i, g_cnt_i);
    cudaGetSymbolAddress((void**)&p_off_u, g_off_u);
    cudaGetSymbolAddress((void**)&p_off_i, g_off_i);
    cudaGetSymbolAddress((void**)&p_woff_u, g_woff_u);
    cudaGetSymbolAddress((void**)&p_woff_i, g_woff_i);
    cudaGetSymbolAddress((void**)&p_ssrc_u2i, g_ssrc_u2i);
    cudaGetSymbolAddress((void**)&p_ssrc_i2u, g_ssrc_i2u);
    cudaGetSymbolAddress((void**)&p_bsum_u, g_bsum_u);
    cudaGetSymbolAddress((void**)&p_bsum_i, g_bsum_i);

    cudaFuncSetAttribute(comp_k, cudaFuncAttributeMaxDynamicSharedMemorySize, COMP_SMEM);

    const int TB = 256;

    // launches 1-5: CSR build + fp16 shadows
    prep_k<<<((NU + NI) * DD / 4 + TB - 1) / TB, TB>>>(x_user, x_item, p_xu16, p_xi16,
                                                       p_cnt_i, p_cnt_u);
    count2_k<<<(2 * NE + TB - 1) / TB, TB>>>(dst_u2i, dst_i2u, p_cnt_i, p_cnt_u);
    bsum2_k<<<NBI + NBU, 1024>>>(p_cnt_i, p_cnt_u, p_bsum_i, p_bsum_u);
    swrite2_k<<<NBI + NBU, 1024>>>(p_cnt_i, p_cnt_u, p_bsum_i, p_bsum_u,
                                   p_off_i, p_off_u, p_woff_i, p_woff_u,
                                   p_inv_i, p_inv_u);
    fill2_k<<<(2 * NE + TB - 1) / TB, TB>>>(src_u2i, dst_u2i, src_i2u, dst_i2u,
                                            p_woff_i, p_woff_u, p_ssrc_u2i, p_ssrc_i2u);

    const int gridAggI = (NI * 16 + TB - 1) / TB;
    const int gridAggU = (NU * 16 + TB - 1) / TB;
    const int GRIDC = 592;  // 4 CTAs/SM x 148 SMs

    // --- layer 0 --- (launch 6 = agg16_k items -> profiled by ncu -s 5 -c 1)
    agg16_k<<<gridAggI, TB>>>(p_xu16, p_off_i, p_ssrc_u2i, p_inv_i, p_agg_i16, NI);
    agg16_k<<<gridAggU, TB>>>(p_xi16, p_off_u, p_ssrc_i2u, p_inv_u, p_agg_u16, NU);
    comp_k<<<GRIDC, TB, COMP_SMEM>>>(p_agg_i16, x_item,
                                     W_rel_u2i, W_root_u2i, b_u2i,
                                     ln_g_item, ln_b_item, p_hi, p_hi16, NI);
    comp_k<<<GRIDC, TB, COMP_SMEM>>>(p_agg_u16, x_user,
                                     W_rel_i2u, W_root_i2u, b_i2u,
                                     ln_g_user, ln_b_user, p_hu, p_hu16, NU);

    // --- layer 1 (writes d_out: users first, then items) ---
    agg16_k<<<gridAggI, TB>>>(p_hu16, p_off_i, p_ssrc_u2i, p_inv_i, p_agg_i16, NI);
    agg16_k<<<gridAggU, TB>>>(p_hi16, p_off_u, p_ssrc_i2u, p_inv_u, p_agg_u16, NU);
    comp_k<<<GRIDC, TB, COMP_SMEM>>>(p_agg_i16, p_hi,
                                     W_rel_u2i + 4096, W_root_u2i + 4096, b_u2i + 64,
                                     ln_g_item + 64, ln_b_item + 64,
                                     out + (size_t)NU * DD, (__half*)0, NI);
    comp_k<<<GRIDC, TB, COMP_SMEM>>>(p_agg_u16, p_hu,
                                     W_rel_i2u + 4096, W_root_i2u + 4096, b_i2u + 64,
                                     ln_g_user + 64, ln_b_user + 64,
                                     out, (__half*)0, NU);
}